// round 8
// baseline (speedup 1.0000x reference)
#include <cuda_runtime.h>
#include <cuda_fp16.h>
#include <math.h>

#define NB   512
#define NPG  128
#define EPG  2048
#define ETOT 1048576
#define KP1  103
#define KP2  83

__device__ float g_h1p[NB * KP1 * 32];
__device__ float g_hsh[NB * NPG * 32];
__device__ int   g_edge2[NB * EPG];
__device__ int   g_ecnt[NB];
__device__ float g_g1[NB * 64];
__device__ float g_gf[NB * 64];

static __device__ __forceinline__ float lrelu(float v) { return v > 0.f ? v : 0.2f * v; }

// ============================================================================
// Stage 1. 384 threads, 2 CTAs/SM, smem 112640 B.
// ============================================================================
__global__ __launch_bounds__(384, 2)
void stage1_kernel(const float* __restrict__ x, const int* __restrict__ ei,
                   const float* __restrict__ Wg, const float* __restrict__ as_w,
                   const float* __restrict__ ad_w, const float* __restrict__ bg,
                   const float* __restrict__ Wt, const float* __restrict__ bt,
                   const float* __restrict__ pw)
{
    extern __shared__ __align__(16) char sm[];
    float4*  xp4   = (float4*)sm;                       // [4096]  65536 B
    uint2*   lgu   = (uint2*)(sm + 65536);              // [2048]  16384 B
    float4*  Wts4  = (float4*)(sm + 81920);             // [1024]  16384 B
    float*   asv   = (float*)(sm + 98304);              // 512 f
    float*   adv   = (float*)(sm + 100352);             // 512 f
    float*   score = (float*)(sm + 102400);             // 128 f
    float*   scratch = (float*)(sm + 102912);           // 1536 f (Wgs+WaSD temp)
    int*     cnt   = (int*)(sm + 109056);               // 128
    int*     offs  = (int*)(sm + 109568);               // 129
    unsigned char* srcl = (unsigned char*)(sm + 110084);// 2048
    // aliases into xp4 region (valid only after aggregation)
    float* red   = (float*)sm;                          // 12*32
    float* red2  = (float*)(sm + 1536);                 // 12*32
    int*   nidx  = (int*)(sm + 3072);                   // 128
    int*   masks = (int*)(sm + 3584);                   // 4
    int*   ec    = (int*)(sm + 3600);                   // 1

    const int g = blockIdx.x, t = threadIdx.x;
    const int lane = t & 31, warp = t >> 5;
    const int gbase = g * EPG;
    float* Wgs  = scratch;           // 1408 f, live during xp phase only
    float* WaSD = scratch + 1408;    // 88 f,  live during xp phase only

    for (int i = t; i < 1024; i += 384) {
        int c4 = i >> 5, o = i & 31;
        Wts4[i] = make_float4(__ldg(Wt + (4 * c4 + 0) * 32 + o),
                              __ldg(Wt + (4 * c4 + 1) * 32 + o),
                              __ldg(Wt + (4 * c4 + 2) * 32 + o),
                              __ldg(Wt + (4 * c4 + 3) * 32 + o));
    }
    for (int i = t; i < 1408; i += 384) Wgs[i] = __ldg(Wg + i);
    if (t < 88) {
        int k = t >> 3, j = t & 7, h = j & 3;
        const float* aw = (j < 4) ? as_w : ad_w;
        float s = 0.f;
        #pragma unroll
        for (int c = 0; c < 32; c++)
            s += __ldg(Wg + k * 128 + h * 32 + c) * __ldg(aw + h * 32 + c);
        WaSD[t] = s;
    }
    if (t < 128) cnt[t] = 0;
    __syncthreads();

    // xp (permuted float4 layout) + folded asv/adv
    for (int n = warp; n < 128; n += 12) {
        const float* xr = x + (size_t)(g * NPG + n) * 11;
        float xv[11];
        #pragma unroll
        for (int k = 0; k < 11; k++) xv[k] = __ldg(xr + k);
        float4 a = {0.f, 0.f, 0.f, 0.f};
        float att = 0.f;
        int j8 = lane & 7;
        #pragma unroll
        for (int k = 0; k < 11; k++) {
            a.x += xv[k] * Wgs[k * 128 + lane];
            a.y += xv[k] * Wgs[k * 128 + 32 + lane];
            a.z += xv[k] * Wgs[k * 128 + 64 + lane];
            a.w += xv[k] * Wgs[k * 128 + 96 + lane];
            att += xv[k] * WaSD[k * 8 + j8];
        }
        xp4[n * 32 + lane] = a;
        if (lane < 4) asv[n * 4 + lane] = att;
        else if (lane < 8) adv[n * 4 + lane - 4] = att;
    }
    __syncthreads();

    // CSR: count, scan, place (+ precompute edge exp into fp16)
    for (int e = t; e < EPG; e += 384)
        atomicAdd(&cnt[ei[ETOT + gbase + e] - g * NPG], 1);
    __syncthreads();
    if (warp == 0) {
        int b = lane * 4;
        int v0 = cnt[b], v1 = cnt[b + 1], v2 = cnt[b + 2], v3 = cnt[b + 3];
        int s = v0 + v1 + v2 + v3, incl = s;
        #pragma unroll
        for (int o = 1; o < 32; o <<= 1) {
            int u = __shfl_up_sync(0xffffffffu, incl, o);
            if (lane >= o) incl += u;
        }
        int base = incl - s;
        offs[b] = base; offs[b + 1] = base + v0;
        offs[b + 2] = base + v0 + v1; offs[b + 3] = base + v0 + v1 + v2;
        if (lane == 31) offs[128] = incl;
        cnt[b] = 0; cnt[b + 1] = 0; cnt[b + 2] = 0; cnt[b + 3] = 0;
    }
    __syncthreads();
    for (int e = t; e < EPG; e += 384) {
        int s = ei[gbase + e] - g * NPG;
        int d = ei[ETOT + gbase + e] - g * NPG;
        int pos = offs[d] + atomicAdd(&cnt[d], 1);
        srcl[pos] = (unsigned char)s;
        float4 av = ((const float4*)asv)[s];
        float4 dv = ((const float4*)adv)[d];
        __half2 e01 = __floats2half2_rn(__expf(lrelu(av.x + dv.x)),
                                        __expf(lrelu(av.y + dv.y)));
        __half2 e23 = __floats2half2_rn(__expf(lrelu(av.z + dv.z)),
                                        __expf(lrelu(av.w + dv.w)));
        uint2 u;
        u.x = *(unsigned int*)&e01;
        u.y = *(unsigned int*)&e23;
        lgu[pos] = u;
    }
    __syncthreads();

    // per-dst aggregation + W_t GEMM + score (fused)
    {
        float4 bgv = make_float4(__ldg(bg + lane), __ldg(bg + 32 + lane),
                                 __ldg(bg + 64 + lane), __ldg(bg + 96 + lane));
        float btl = __ldg(bt + lane);
        float pwl = __ldg(pw + lane);
        float ssn = pwl * pwl;
        #pragma unroll
        for (int off = 16; off; off >>= 1) ssn += __shfl_xor_sync(0xffffffffu, ssn, off);
        float pwinv = rsqrtf(ssn);
        float* scr = scratch + warp * 128;
        float4* scr4 = (float4*)scr;
        for (int d = warp; d < 128; d += 12) {
            int o0 = offs[d], dg = offs[d + 1] - o0;
            float slv = asv[d * 4 + (lane & 3)] + adv[d * 4 + (lane & 3)];
            float sev = __expf(lrelu(slv));
            float4 den;
            den.x = __shfl_sync(0xffffffffu, sev, 0);
            den.y = __shfl_sync(0xffffffffu, sev, 1);
            den.z = __shfl_sync(0xffffffffu, sev, 2);
            den.w = __shfl_sync(0xffffffffu, sev, 3);
            float4 xv = xp4[d * 32 + lane];
            float4 acc = {den.x * xv.x, den.y * xv.y, den.z * xv.z, den.w * xv.w};
            #pragma unroll 4
            for (int k = 0; k < dg; k++) {
                int s = srcl[o0 + k];
                uint2 lu = lgu[o0 + k];
                float2 f0 = __half22float2(*(__half2*)&lu.x);
                float2 f1 = __half22float2(*(__half2*)&lu.y);
                float4 xs = xp4[s * 32 + lane];
                acc.x += f0.x * xs.x; acc.y += f0.y * xs.y;
                acc.z += f1.x * xs.z; acc.w += f1.y * xs.w;
                den.x += f0.x; den.y += f0.y; den.z += f1.x; den.w += f1.y;
            }
            float4 r;
            r.x = fmaxf(acc.x / (den.x + 1e-16f) + bgv.x, 0.f);
            r.y = fmaxf(acc.y / (den.y + 1e-16f) + bgv.y, 0.f);
            r.z = fmaxf(acc.z / (den.z + 1e-16f) + bgv.z, 0.f);
            r.w = fmaxf(acc.w / (den.w + 1e-16f) + bgv.w, 0.f);
            scr[lane] = r.x; scr[32 + lane] = r.y;
            scr[64 + lane] = r.z; scr[96 + lane] = r.w;
            __syncwarp();
            float a = btl;
            #pragma unroll 8
            for (int c4 = 0; c4 < 32; c4++) {
                float4 rr = scr4[c4];
                float4 w = Wts4[c4 * 32 + lane];
                a += rr.x * w.x + rr.y * w.y + rr.z * w.z + rr.w * w.w;
            }
            g_hsh[(size_t)g * 4096 + d * 32 + lane] = a;
            float p = a * pwl;
            #pragma unroll
            for (int off = 16; off; off >>= 1) p += __shfl_xor_sync(0xffffffffu, p, off);
            if (lane == 0) score[d] = tanhf(p * pwinv);
            __syncwarp();
        }
    }
    __syncthreads();   // xp4 dead; aliases live

    // stable top-K rank + compaction indices
    if (t < 128) {
        float sc = score[t]; int r = 0;
        for (int m = 0; m < 128; m++) {
            float v = score[m];
            r += (v > sc) || (v == sc && m < t);
        }
        int keep = (r < KP1);
        unsigned bm = __ballot_sync(0xffffffffu, keep);
        if (lane == 0) masks[warp] = (int)bm;
        nidx[t] = keep;
    }
    if (t == 383) *ec = 0;
    __syncthreads();
    if (t < 128) {
        int before = 0;
        for (int w2 = 0; w2 < warp; w2++) before += __popc((unsigned)masks[w2]);
        before += __popc((unsigned)masks[warp] & ((1u << lane) - 1u));
        nidx[t] = nidx[t] ? before : -1;
    }
    __syncthreads();

    // pooled features + partial readout
    {
        int o = t & 31, grp = t >> 5;
        float m2 = -1e30f, su = 0.f;
        for (int n = grp; n < 128; n += 12) {
            int ni = nidx[n];
            if (ni >= 0) {
                float v = g_hsh[(size_t)g * 4096 + n * 32 + o] * score[n];
                m2 = fmaxf(m2, v); su += v;
                g_h1p[((size_t)g * KP1 + ni) * 32 + o] = v;
            }
        }
        red[grp * 32 + o] = m2; red2[grp * 32 + o] = su;
    }
    // edge remap
    for (int e = t; e < EPG; e += 384) {
        int ns = nidx[ei[gbase + e] - g * NPG];
        int nd = nidx[ei[ETOT + gbase + e] - g * NPG];
        int valid = (ns >= 0 && nd >= 0);
        unsigned bm = __ballot_sync(0xffffffffu, valid);
        int base;
        if (lane == 0) base = atomicAdd(ec, __popc(bm));
        base = __shfl_sync(0xffffffffu, base, 0);
        if (valid)
            g_edge2[gbase + base + __popc(bm & ((1u << lane) - 1u))] = (ns << 8) | nd;
    }
    __syncthreads();
    if (t < 32) {
        float m2 = -1e30f, su = 0.f;
        #pragma unroll
        for (int k = 0; k < 12; k++) {
            m2 = fmaxf(m2, red[k * 32 + t]); su += red2[k * 32 + t];
        }
        g_g1[g * 64 + t] = m2;
        g_g1[g * 64 + 32 + t] = su / (float)KP1;
    }
    if (t == 0) g_ecnt[g] = *ec;
}

// ============================================================================
// Stage 2. 384 threads, 2 CTAs/SM, smem 98304 B.
// ============================================================================
__global__ __launch_bounds__(384, 2)
void stage2_kernel(const float* __restrict__ Wg, const float* __restrict__ as_w,
                   const float* __restrict__ ad_w, const float* __restrict__ bg,
                   const float* __restrict__ Wt, const float* __restrict__ bt,
                   const float* __restrict__ pw)
{
    extern __shared__ __align__(16) char sm[];
    float4*  xp4   = (float4*)sm;                       // [103*32] 52736 B
    uint2*   lgu   = (uint2*)(sm + 52736);              // 16384 B (Wg2p temp first)
    float4*  Wg2p  = (float4*)(sm + 52736);
    float4*  Wts4  = (float4*)(sm + 69120);             // 16384 B
    float*   asv   = (float*)(sm + 85504);              // 412 f
    float*   adv   = (float*)(sm + 87168);
    float*   score = (float*)(sm + 88832);
    float*   scratch = (float*)(sm + 89248);            // 6144 B (WaSD2 temp first)
    float*   WaSD2 = scratch;                           // 256 f, xp phase only
    int*     cnt   = (int*)(sm + 95392);
    int*     offs  = (int*)(sm + 95808);
    unsigned char* srcl = (unsigned char*)(sm + 96228);
    float* red   = (float*)sm;
    float* red2  = (float*)(sm + 1536);
    int*   nidx  = (int*)(sm + 3072);

    const int g = blockIdx.x, t = threadIdx.x;
    const int lane = t & 31, warp = t >> 5;
    const int ne = g_ecnt[g];

    for (int i = t; i < 1024; i += 384) {
        int c4 = i >> 5, o = i & 31;
        Wts4[i] = make_float4(__ldg(Wt + (4 * c4 + 0) * 32 + o),
                              __ldg(Wt + (4 * c4 + 1) * 32 + o),
                              __ldg(Wt + (4 * c4 + 2) * 32 + o),
                              __ldg(Wt + (4 * c4 + 3) * 32 + o));
        int k = i >> 5, l = i & 31;
        Wg2p[i] = make_float4(__ldg(Wg + k * 128 + l),
                              __ldg(Wg + k * 128 + 32 + l),
                              __ldg(Wg + k * 128 + 64 + l),
                              __ldg(Wg + k * 128 + 96 + l));
    }
    if (t < 256) {
        int k = t >> 3, j = t & 7, h = j & 3;
        const float* aw = (j < 4) ? as_w : ad_w;
        float s = 0.f;
        #pragma unroll
        for (int c = 0; c < 32; c++)
            s += __ldg(Wg + k * 128 + h * 32 + c) * __ldg(aw + h * 32 + c);
        WaSD2[t] = s;
    }
    if (t < 104) cnt[t] = 0;
    __syncthreads();

    // xp + folded asv/adv inside the shuffle GEMM loop
    for (int n = warp; n < KP1; n += 12) {
        float hv = __ldg(g_h1p + ((size_t)g * KP1 + n) * 32 + lane);
        float4 a = {0.f, 0.f, 0.f, 0.f};
        float att = 0.f;
        int j8 = lane & 7;
        #pragma unroll
        for (int k = 0; k < 32; k++) {
            float tv = __shfl_sync(0xffffffffu, hv, k);
            float4 w = Wg2p[k * 32 + lane];
            a.x += tv * w.x; a.y += tv * w.y; a.z += tv * w.z; a.w += tv * w.w;
            att += tv * WaSD2[k * 8 + j8];
        }
        xp4[n * 32 + lane] = a;
        if (lane < 4) asv[n * 4 + lane] = att;
        else if (lane < 8) adv[n * 4 + lane - 4] = att;
    }
    __syncthreads();

    for (int e = t; e < ne; e += 384)
        atomicAdd(&cnt[g_edge2[g * EPG + e] & 255], 1);
    __syncthreads();
    if (warp == 0 && lane < 26) {
        int b = lane * 4;
        int v0 = cnt[b], v1 = cnt[b + 1], v2 = cnt[b + 2], v3 = cnt[b + 3];
        int s = v0 + v1 + v2 + v3, incl = s;
        #pragma unroll
        for (int o = 1; o < 32; o <<= 1) {
            int u = __shfl_up_sync(0x03ffffffu, incl, o);
            if (lane >= o) incl += u;
        }
        int base = incl - s;
        offs[b] = base; offs[b + 1] = base + v0;
        offs[b + 2] = base + v0 + v1; offs[b + 3] = base + v0 + v1 + v2;
        cnt[b] = 0; cnt[b + 1] = 0; cnt[b + 2] = 0; cnt[b + 3] = 0;
    }
    __syncthreads();
    for (int e = t; e < ne; e += 384) {
        int pk = g_edge2[g * EPG + e];
        int s = pk >> 8, d = pk & 255;
        int pos = offs[d] + atomicAdd(&cnt[d], 1);
        srcl[pos] = (unsigned char)s;
        float4 av = ((const float4*)asv)[s];
        float4 dv = ((const float4*)adv)[d];
        __half2 e01 = __floats2half2_rn(__expf(lrelu(av.x + dv.x)),
                                        __expf(lrelu(av.y + dv.y)));
        __half2 e23 = __floats2half2_rn(__expf(lrelu(av.z + dv.z)),
                                        __expf(lrelu(av.w + dv.w)));
        uint2 u;
        u.x = *(unsigned int*)&e01;
        u.y = *(unsigned int*)&e23;
        lgu[pos] = u;
    }
    __syncthreads();

    {
        float4 bgv = make_float4(__ldg(bg + lane), __ldg(bg + 32 + lane),
                                 __ldg(bg + 64 + lane), __ldg(bg + 96 + lane));
        float btl = __ldg(bt + lane);
        float pwl = __ldg(pw + lane);
        float ssn = pwl * pwl;
        #pragma unroll
        for (int off = 16; off; off >>= 1) ssn += __shfl_xor_sync(0xffffffffu, ssn, off);
        float pwinv = rsqrtf(ssn);
        float* scr = scratch + warp * 128;
        float4* scr4 = (float4*)scr;
        for (int d = warp; d < KP1; d += 12) {
            int o0 = offs[d], dg = offs[d + 1] - o0;
            float slv = asv[d * 4 + (lane & 3)] + adv[d * 4 + (lane & 3)];
            float sev = __expf(lrelu(slv));
            float4 den;
            den.x = __shfl_sync(0xffffffffu, sev, 0);
            den.y = __shfl_sync(0xffffffffu, sev, 1);
            den.z = __shfl_sync(0xffffffffu, sev, 2);
            den.w = __shfl_sync(0xffffffffu, sev, 3);
            float4 xv = xp4[d * 32 + lane];
            float4 acc = {den.x * xv.x, den.y * xv.y, den.z * xv.z, den.w * xv.w};
            #pragma unroll 4
            for (int k = 0; k < dg; k++) {
                int s = srcl[o0 + k];
                uint2 lu = lgu[o0 + k];
                float2 f0 = __half22float2(*(__half2*)&lu.x);
                float2 f1 = __half22float2(*(__half2*)&lu.y);
                float4 xs = xp4[s * 32 + lane];
                acc.x += f0.x * xs.x; acc.y += f0.y * xs.y;
                acc.z += f1.x * xs.z; acc.w += f1.y * xs.w;
                den.x += f0.x; den.y += f0.y; den.z += f1.x; den.w += f1.y;
            }
            float4 r;
            r.x = fmaxf(acc.x / (den.x + 1e-16f) + bgv.x, 0.f);
            r.y = fmaxf(acc.y / (den.y + 1e-16f) + bgv.y, 0.f);
            r.z = fmaxf(acc.z / (den.z + 1e-16f) + bgv.z, 0.f);
            r.w = fmaxf(acc.w / (den.w + 1e-16f) + bgv.w, 0.f);
            scr[lane] = r.x; scr[32 + lane] = r.y;
            scr[64 + lane] = r.z; scr[96 + lane] = r.w;
            __syncwarp();
            float a = btl;
            #pragma unroll 8
            for (int c4 = 0; c4 < 32; c4++) {
                float4 rr = scr4[c4];
                float4 w = Wts4[c4 * 32 + lane];
                a += rr.x * w.x + rr.y * w.y + rr.z * w.z + rr.w * w.w;
            }
            g_hsh[(size_t)g * 4096 + d * 32 + lane] = a;
            float p = a * pwl;
            #pragma unroll
            for (int off = 16; off; off >>= 1) p += __shfl_xor_sync(0xffffffffu, p, off);
            if (lane == 0) score[d] = tanhf(p * pwinv);
            __syncwarp();
        }
    }
    __syncthreads();

    if (t < KP1) {
        float sc = score[t]; int r = 0;
        for (int m = 0; m < KP1; m++) {
            float v = score[m];
            r += (v > sc) || (v == sc && m < t);
        }
        nidx[t] = (r < KP2) ? 1 : 0;
    }
    __syncthreads();
    {
        int o = t & 31, grp = t >> 5;
        float m2 = -1e30f, su = 0.f;
        for (int n = grp; n < KP1; n += 12) {
            if (nidx[n]) {
                float v = g_hsh[(size_t)g * 4096 + n * 32 + o] * score[n];
                m2 = fmaxf(m2, v); su += v;
            }
        }
        red[grp * 32 + o] = m2; red2[grp * 32 + o] = su;
    }
    __syncthreads();
    if (t < 32) {
        float m2 = -1e30f, su = 0.f;
        #pragma unroll
        for (int k = 0; k < 12; k++) {
            m2 = fmaxf(m2, red[k * 32 + t]); su += red2[k * 32 + t];
        }
        g_gf[g * 64 + t]      = g_g1[g * 64 + t]      + m2;
        g_gf[g * 64 + 32 + t] = g_g1[g * 64 + 32 + t] + su / (float)KP2;
    }
}

// ============================================================================
// Stage 3: MLP 64 -> 256 -> 1024 -> 1. 64 blocks x 8 graphs.
// ============================================================================
__global__ __launch_bounds__(256, 1)
void mlp_kernel(const float* __restrict__ Wl1, const float* __restrict__ bl1,
                const float* __restrict__ Wl2, const float* __restrict__ bl2,
                const float* __restrict__ Wl3, const float* __restrict__ bl3,
                float* __restrict__ out)
{
    __shared__ float gsh[8][64];
    __shared__ __align__(16) float t1[8][256];
    __shared__ __align__(16) float wl3s[1024];
    __shared__ float redw[8][8];
    const int rb = blockIdx.x * 8;
    const int t = threadIdx.x, lane = t & 31, warp = t >> 5;

    for (int i = t; i < 1024; i += 256) wl3s[i] = Wl3[i];
    for (int i = t; i < 512; i += 256) ((float*)gsh)[i] = g_gf[rb * 64 + i];
    __syncthreads();
    for (int i = t; i < 2048; i += 256) {
        int r = i >> 8, j = i & 255;
        float a = bl1[j];
        #pragma unroll 8
        for (int k = 0; k < 64; k++) a += gsh[r][k] * Wl1[k * 256 + j];
        t1[r][j] = fmaxf(a, 0.f);
    }
    __syncthreads();
    const int jg = t;
    float4 acc[8];
    {
        float4 b2 = ((const float4*)bl2)[jg];
        #pragma unroll
        for (int r = 0; r < 8; r++) acc[r] = b2;
    }
    const float4* W2 = (const float4*)Wl2;
    for (int k4 = 0; k4 < 64; k4++) {
        float4 w0 = W2[(k4 * 4 + 0) * 256 + jg];
        float4 w1 = W2[(k4 * 4 + 1) * 256 + jg];
        float4 w2 = W2[(k4 * 4 + 2) * 256 + jg];
        float4 w3 = W2[(k4 * 4 + 3) * 256 + jg];
        #pragma unroll
        for (int r = 0; r < 8; r++) {
            float4 tv = ((const float4*)t1[r])[k4];
            acc[r].x += tv.x * w0.x + tv.y * w1.x + tv.z * w2.x + tv.w * w3.x;
            acc[r].y += tv.x * w0.y + tv.y * w1.y + tv.z * w2.y + tv.w * w3.y;
            acc[r].z += tv.x * w0.z + tv.y * w1.z + tv.z * w2.z + tv.w * w3.z;
            acc[r].w += tv.x * w0.w + tv.y * w1.w + tv.z * w2.w + tv.w * w3.w;
        }
    }
    float4 w3v = ((const float4*)wl3s)[jg];
    #pragma unroll
    for (int r = 0; r < 8; r++) {
        float p = fmaxf(acc[r].x, 0.f) * w3v.x + fmaxf(acc[r].y, 0.f) * w3v.y +
                  fmaxf(acc[r].z, 0.f) * w3v.z + fmaxf(acc[r].w, 0.f) * w3v.w;
        #pragma unroll
        for (int m = 16; m; m >>= 1) p += __shfl_xor_sync(0xffffffffu, p, m);
        if (lane == 0) redw[r][warp] = p;
    }
    __syncthreads();
    if (t < 8) {
        float s = bl3[0];
        #pragma unroll
        for (int w2 = 0; w2 < 8; w2++) s += redw[t][w2];
        out[rb + t] = s;
    }
}

// ============================================================================
extern "C" void kernel_launch(void* const* d_in, const int* in_sizes, int n_in,
                              void* d_out, int out_size)
{
    const float* x   = (const float*)d_in[0];
    const int*   ei  = (const int*)d_in[1];
    const float* Wg1 = (const float*)d_in[4];
    const float* as1 = (const float*)d_in[5];
    const float* ad1 = (const float*)d_in[6];
    const float* bg1 = (const float*)d_in[7];
    const float* Wt1 = (const float*)d_in[8];
    const float* bt1 = (const float*)d_in[9];
    const float* pw1 = (const float*)d_in[10];
    const float* Wg2 = (const float*)d_in[11];
    const float* as2 = (const float*)d_in[12];
    const float* ad2 = (const float*)d_in[13];
    const float* bg2 = (const float*)d_in[14];
    const float* Wt2 = (const float*)d_in[15];
    const float* bt2 = (const float*)d_in[16];
    const float* pw2 = (const float*)d_in[17];
    const float* Wl1 = (const float*)d_in[18];
    const float* bl1 = (const float*)d_in[19];
    const float* Wl2 = (const float*)d_in[20];
    const float* bl2 = (const float*)d_in[21];
    const float* Wl3 = (const float*)d_in[22];
    const float* bl3 = (const float*)d_in[23];
    float* out = (float*)d_out;

    const int SM1B = 112640;
    const int SM2B = 98304;
    cudaFuncSetAttribute(stage1_kernel, cudaFuncAttributeMaxDynamicSharedMemorySize, SM1B);
    cudaFuncSetAttribute(stage2_kernel, cudaFuncAttributeMaxDynamicSharedMemorySize, SM2B);

    stage1_kernel<<<NB, 384, SM1B>>>(x, ei, Wg1, as1, ad1, bg1, Wt1, bt1, pw1);
    stage2_kernel<<<NB, 384, SM2B>>>(Wg2, as2, ad2, bg2, Wt2, bt2, pw2);
    mlp_kernel<<<NB / 8, 256>>>(Wl1, bl1, Wl2, bl2, Wl3, bl3, out);
}

// round 13
// speedup vs baseline: 1.0375x; 1.0375x over previous
#include <cuda_runtime.h>
#include <cuda_fp16.h>
#include <math.h>

#define NB   512
#define NPG  128
#define EPG  2048
#define ETOT 1048576
#define KP1  103
#define KP2  83

__device__ float g_h1p[NB * KP1 * 32];
__device__ float g_hsh[NB * NPG * 32];
__device__ int   g_edge2[NB * EPG];
__device__ int   g_ecnt[NB];
__device__ float g_g1[NB * 64];
__device__ float g_gf[NB * 64];

static __device__ __forceinline__ float lrelu(float v) { return v > 0.f ? v : 0.2f * v; }

// ============================================================================
// Stage 1. 384 threads, 2 CTAs/SM, smem 112640 B.
// ============================================================================
__global__ __launch_bounds__(384, 2)
void stage1_kernel(const float* __restrict__ x, const int* __restrict__ ei,
                   const float* __restrict__ Wg, const float* __restrict__ as_w,
                   const float* __restrict__ ad_w, const float* __restrict__ bg,
                   const float* __restrict__ Wt, const float* __restrict__ bt,
                   const float* __restrict__ pw)
{
    extern __shared__ __align__(16) char sm[];
    float4*  xp4   = (float4*)sm;                       // [4096]  65536 B
    uint2*   lgu   = (uint2*)(sm + 65536);              // [2048]  16384 B
    float4*  Wts4  = (float4*)(sm + 81920);             // [1024]  16384 B
    float*   asv   = (float*)(sm + 98304);              // 512 f
    float*   adv   = (float*)(sm + 100352);             // 512 f
    float*   score = (float*)(sm + 102400);             // 128 f
    float*   scratch = (float*)(sm + 102912);           // 1536 f (aliased temps)
    int*     cnt   = (int*)(sm + 109056);               // 128
    int*     offs  = (int*)(sm + 109568);               // 129
    unsigned char* srcl = (unsigned char*)(sm + 110084);// 2048
    // aliases into xp4 region (valid only after aggregation)
    float* red   = (float*)sm;                          // 12*32
    float* red2  = (float*)(sm + 1536);                 // 12*32
    int*   nidx  = (int*)(sm + 3072);                   // 128
    int*   masks = (int*)(sm + 3584);                   // 4
    int*   ec    = (int*)(sm + 3600);                   // 1

    const int g = blockIdx.x, t = threadIdx.x;
    const int lane = t & 31, warp = t >> 5;
    const int gbase = g * EPG;
    float* Wgs  = scratch;                      // 1408 f, xp phase only
    float* WaSD = scratch + 1408;               // 88 f,   xp phase only
    unsigned short* stash = (unsigned short*)scratch;  // 2048 us, CSR phase only

    for (int i = t; i < 1024; i += 384) {
        int c4 = i >> 5, o = i & 31;
        Wts4[i] = make_float4(__ldg(Wt + (4 * c4 + 0) * 32 + o),
                              __ldg(Wt + (4 * c4 + 1) * 32 + o),
                              __ldg(Wt + (4 * c4 + 2) * 32 + o),
                              __ldg(Wt + (4 * c4 + 3) * 32 + o));
    }
    for (int i = t; i < 1408; i += 384) Wgs[i] = __ldg(Wg + i);
    if (t < 88) {
        int k = t >> 3, j = t & 7, h = j & 3;
        const float* aw = (j < 4) ? as_w : ad_w;
        float s = 0.f;
        #pragma unroll
        for (int c = 0; c < 32; c++)
            s += __ldg(Wg + k * 128 + h * 32 + c) * __ldg(aw + h * 32 + c);
        WaSD[t] = s;
    }
    if (t < 128) cnt[t] = 0;
    __syncthreads();

    // xp (permuted float4 layout) + folded asv/adv
    for (int n = warp; n < 128; n += 12) {
        const float* xr = x + (size_t)(g * NPG + n) * 11;
        float xv[11];
        #pragma unroll
        for (int k = 0; k < 11; k++) xv[k] = __ldg(xr + k);
        float4 a = {0.f, 0.f, 0.f, 0.f};
        float att = 0.f;
        int j8 = lane & 7;
        #pragma unroll
        for (int k = 0; k < 11; k++) {
            a.x += xv[k] * Wgs[k * 128 + lane];
            a.y += xv[k] * Wgs[k * 128 + 32 + lane];
            a.z += xv[k] * Wgs[k * 128 + 64 + lane];
            a.w += xv[k] * Wgs[k * 128 + 96 + lane];
            att += xv[k] * WaSD[k * 8 + j8];
        }
        xp4[n * 32 + lane] = a;
        if (lane < 4) asv[n * 4 + lane] = att;
        else if (lane < 8) adv[n * 4 + lane - 4] = att;
    }
    __syncthreads();   // Wgs/WaSD dead; stash region live next

    // CSR count pass: load edges once, stash packed (s<<8)|d
    for (int e = t; e < EPG; e += 384) {
        int s = ei[gbase + e] - g * NPG;
        int d = ei[ETOT + gbase + e] - g * NPG;
        stash[e] = (unsigned short)((s << 8) | d);
        atomicAdd(&cnt[d], 1);
    }
    __syncthreads();
    if (warp == 0) {
        int b = lane * 4;
        int v0 = cnt[b], v1 = cnt[b + 1], v2 = cnt[b + 2], v3 = cnt[b + 3];
        int s = v0 + v1 + v2 + v3, incl = s;
        #pragma unroll
        for (int o = 1; o < 32; o <<= 1) {
            int u = __shfl_up_sync(0xffffffffu, incl, o);
            if (lane >= o) incl += u;
        }
        int base = incl - s;
        offs[b] = base; offs[b + 1] = base + v0;
        offs[b + 2] = base + v0 + v1; offs[b + 3] = base + v0 + v1 + v2;
        if (lane == 31) offs[128] = incl;
        cnt[b] = 0; cnt[b + 1] = 0; cnt[b + 2] = 0; cnt[b + 3] = 0;
    }
    __syncthreads();
    // place pass: CSR fill + precomputed fp16 edge exp (no global loads)
    for (int e = t; e < EPG; e += 384) {
        int pk = stash[e];
        int s = pk >> 8, d = pk & 255;
        int pos = offs[d] + atomicAdd(&cnt[d], 1);
        srcl[pos] = (unsigned char)s;
        float4 av = ((const float4*)asv)[s];
        float4 dv = ((const float4*)adv)[d];
        __half2 e01 = __floats2half2_rn(__expf(lrelu(av.x + dv.x)),
                                        __expf(lrelu(av.y + dv.y)));
        __half2 e23 = __floats2half2_rn(__expf(lrelu(av.z + dv.z)),
                                        __expf(lrelu(av.w + dv.w)));
        uint2 u;
        u.x = *(unsigned int*)&e01;
        u.y = *(unsigned int*)&e23;
        lgu[e < 0 ? 0 : pos] = u;
    }
    __syncthreads();

    // per-dst aggregation + W_t GEMM + score (fused)
    {
        float4 bgv = make_float4(__ldg(bg + lane), __ldg(bg + 32 + lane),
                                 __ldg(bg + 64 + lane), __ldg(bg + 96 + lane));
        float btl = __ldg(bt + lane);
        float pwl = __ldg(pw + lane);
        float ssn = pwl * pwl;
        #pragma unroll
        for (int off = 16; off; off >>= 1) ssn += __shfl_xor_sync(0xffffffffu, ssn, off);
        float pwinv = rsqrtf(ssn);
        float* scr = scratch + warp * 128;
        float4* scr4 = (float4*)scr;
        for (int d = warp; d < 128; d += 12) {
            int o0 = offs[d], dg = offs[d + 1] - o0;
            float slv = asv[d * 4 + (lane & 3)] + adv[d * 4 + (lane & 3)];
            float sev = __expf(lrelu(slv));
            float4 den;
            den.x = __shfl_sync(0xffffffffu, sev, 0);
            den.y = __shfl_sync(0xffffffffu, sev, 1);
            den.z = __shfl_sync(0xffffffffu, sev, 2);
            den.w = __shfl_sync(0xffffffffu, sev, 3);
            float4 xv = xp4[d * 32 + lane];
            float4 acc = {den.x * xv.x, den.y * xv.y, den.z * xv.z, den.w * xv.w};
            #pragma unroll 4
            for (int k = 0; k < dg; k++) {
                int s = srcl[o0 + k];
                uint2 lu = lgu[o0 + k];
                float2 f0 = __half22float2(*(__half2*)&lu.x);
                float2 f1 = __half22float2(*(__half2*)&lu.y);
                float4 xs = xp4[s * 32 + lane];
                acc.x += f0.x * xs.x; acc.y += f0.y * xs.y;
                acc.z += f1.x * xs.z; acc.w += f1.y * xs.w;
                den.x += f0.x; den.y += f0.y; den.z += f1.x; den.w += f1.y;
            }
            float4 r;
            r.x = fmaxf(__fdividef(acc.x, den.x) + bgv.x, 0.f);
            r.y = fmaxf(__fdividef(acc.y, den.y) + bgv.y, 0.f);
            r.z = fmaxf(__fdividef(acc.z, den.z) + bgv.z, 0.f);
            r.w = fmaxf(__fdividef(acc.w, den.w) + bgv.w, 0.f);
            scr[lane] = r.x; scr[32 + lane] = r.y;
            scr[64 + lane] = r.z; scr[96 + lane] = r.w;
            __syncwarp();
            float a = btl;
            #pragma unroll 8
            for (int c4 = 0; c4 < 32; c4++) {
                float4 rr = scr4[c4];
                float4 w = Wts4[c4 * 32 + lane];
                a += rr.x * w.x + rr.y * w.y + rr.z * w.z + rr.w * w.w;
            }
            g_hsh[(size_t)g * 4096 + d * 32 + lane] = a;
            float p = a * pwl;
            #pragma unroll
            for (int off = 16; off; off >>= 1) p += __shfl_xor_sync(0xffffffffu, p, off);
            if (lane == 0) score[d] = tanhf(p * pwinv);
            __syncwarp();
        }
    }
    __syncthreads();   // xp4 dead; aliases live

    // stable top-K rank + compaction indices
    if (t < 128) {
        float sc = score[t]; int r = 0;
        for (int m = 0; m < 128; m++) {
            float v = score[m];
            r += (v > sc) || (v == sc && m < t);
        }
        int keep = (r < KP1);
        unsigned bm = __ballot_sync(0xffffffffu, keep);
        if (lane == 0) masks[warp] = (int)bm;
        nidx[t] = keep;
    }
    if (t == 383) *ec = 0;
    __syncthreads();
    if (t < 128) {
        int before = 0;
        for (int w2 = 0; w2 < warp; w2++) before += __popc((unsigned)masks[w2]);
        before += __popc((unsigned)masks[warp] & ((1u << lane) - 1u));
        nidx[t] = nidx[t] ? before : -1;
    }
    __syncthreads();

    // pooled features + partial readout
    {
        int o = t & 31, grp = t >> 5;
        float m2 = -1e30f, su = 0.f;
        for (int n = grp; n < 128; n += 12) {
            int ni = nidx[n];
            if (ni >= 0) {
                float v = g_hsh[(size_t)g * 4096 + n * 32 + o] * score[n];
                m2 = fmaxf(m2, v); su += v;
                g_h1p[((size_t)g * KP1 + ni) * 32 + o] = v;
            }
        }
        red[grp * 32 + o] = m2; red2[grp * 32 + o] = su;
    }
    // edge remap (ei re-reads hit L1)
    for (int e = t; e < EPG; e += 384) {
        int ns = nidx[ei[gbase + e] - g * NPG];
        int nd = nidx[ei[ETOT + gbase + e] - g * NPG];
        int valid = (ns >= 0 && nd >= 0);
        unsigned bm = __ballot_sync(0xffffffffu, valid);
        int base;
        if (lane == 0) base = atomicAdd(ec, __popc(bm));
        base = __shfl_sync(0xffffffffu, base, 0);
        if (valid)
            g_edge2[gbase + base + __popc(bm & ((1u << lane) - 1u))] = (ns << 8) | nd;
    }
    __syncthreads();
    if (t < 32) {
        float m2 = -1e30f, su = 0.f;
        #pragma unroll
        for (int k = 0; k < 12; k++) {
            m2 = fmaxf(m2, red[k * 32 + t]); su += red2[k * 32 + t];
        }
        g_g1[g * 64 + t] = m2;
        g_g1[g * 64 + 32 + t] = su / (float)KP1;
    }
    if (t == 0) g_ecnt[g] = *ec;
}

// ============================================================================
// Stage 2. 384 threads, 2 CTAs/SM, smem 98304 B.
// ============================================================================
__global__ __launch_bounds__(384, 2)
void stage2_kernel(const float* __restrict__ Wg, const float* __restrict__ as_w,
                   const float* __restrict__ ad_w, const float* __restrict__ bg,
                   const float* __restrict__ Wt, const float* __restrict__ bt,
                   const float* __restrict__ pw)
{
    extern __shared__ __align__(16) char sm[];
    float4*  xp4   = (float4*)sm;                       // [103*32] 52736 B
    uint2*   lgu   = (uint2*)(sm + 52736);              // 16384 B (Wg2p temp first)
    float4*  Wg2p  = (float4*)(sm + 52736);
    float4*  Wts4  = (float4*)(sm + 69120);             // 16384 B
    float*   asv   = (float*)(sm + 85504);
    float*   adv   = (float*)(sm + 87168);
    float*   score = (float*)(sm + 88832);
    float*   scratch = (float*)(sm + 89248);            // 1536 f (aliased temps)
    int*     cnt   = (int*)(sm + 95392);
    int*     offs  = (int*)(sm + 95808);
    unsigned char* srcl = (unsigned char*)(sm + 96228);
    float* red   = (float*)sm;
    float* red2  = (float*)(sm + 1536);
    int*   nidx  = (int*)(sm + 3072);

    const int g = blockIdx.x, t = threadIdx.x;
    const int lane = t & 31, warp = t >> 5;
    const int ne = g_ecnt[g];
    float* WaSD2 = scratch;                              // 256 f, xp phase only
    unsigned short* stash = (unsigned short*)scratch;    // CSR phase only

    for (int i = t; i < 1024; i += 384) {
        int c4 = i >> 5, o = i & 31;
        Wts4[i] = make_float4(__ldg(Wt + (4 * c4 + 0) * 32 + o),
                              __ldg(Wt + (4 * c4 + 1) * 32 + o),
                              __ldg(Wt + (4 * c4 + 2) * 32 + o),
                              __ldg(Wt + (4 * c4 + 3) * 32 + o));
        int k = i >> 5, l = i & 31;
        Wg2p[i] = make_float4(__ldg(Wg + k * 128 + l),
                              __ldg(Wg + k * 128 + 32 + l),
                              __ldg(Wg + k * 128 + 64 + l),
                              __ldg(Wg + k * 128 + 96 + l));
    }
    if (t < 256) {
        int k = t >> 3, j = t & 7, h = j & 3;
        const float* aw = (j < 4) ? as_w : ad_w;
        float s = 0.f;
        #pragma unroll
        for (int c = 0; c < 32; c++)
            s += __ldg(Wg + k * 128 + h * 32 + c) * __ldg(aw + h * 32 + c);
        WaSD2[t] = s;
    }
    if (t < 104) cnt[t] = 0;
    __syncthreads();

    // xp + folded asv/adv inside the shuffle GEMM loop
    for (int n = warp; n < KP1; n += 12) {
        float hv = __ldg(g_h1p + ((size_t)g * KP1 + n) * 32 + lane);
        float4 a = {0.f, 0.f, 0.f, 0.f};
        float att = 0.f;
        int j8 = lane & 7;
        #pragma unroll
        for (int k = 0; k < 32; k++) {
            float tv = __shfl_sync(0xffffffffu, hv, k);
            float4 w = Wg2p[k * 32 + lane];
            a.x += tv * w.x; a.y += tv * w.y; a.z += tv * w.z; a.w += tv * w.w;
            att += tv * WaSD2[k * 8 + j8];
        }
        xp4[n * 32 + lane] = a;
        if (lane < 4) asv[n * 4 + lane] = att;
        else if (lane < 8) adv[n * 4 + lane - 4] = att;
    }
    __syncthreads();   // WaSD2 dead; stash live next

    for (int e = t; e < ne; e += 384) {
        int pk = g_edge2[g * EPG + e];
        stash[e] = (unsigned short)pk;
        atomicAdd(&cnt[pk & 255], 1);
    }
    __syncthreads();
    if (warp == 0 && lane < 26) {
        int b = lane * 4;
        int v0 = cnt[b], v1 = cnt[b + 1], v2 = cnt[b + 2], v3 = cnt[b + 3];
        int s = v0 + v1 + v2 + v3, incl = s;
        #pragma unroll
        for (int o = 1; o < 32; o <<= 1) {
            int u = __shfl_up_sync(0x03ffffffu, incl, o);
            if (lane >= o) incl += u;
        }
        int base = incl - s;
        offs[b] = base; offs[b + 1] = base + v0;
        offs[b + 2] = base + v0 + v1; offs[b + 3] = base + v0 + v1 + v2;
        cnt[b] = 0; cnt[b + 1] = 0; cnt[b + 2] = 0; cnt[b + 3] = 0;
    }
    __syncthreads();
    for (int e = t; e < ne; e += 384) {
        int pk = stash[e];
        int s = pk >> 8, d = pk & 255;
        int pos = offs[d] + atomicAdd(&cnt[d], 1);
        srcl[pos] = (unsigned char)s;
        float4 av = ((const float4*)asv)[s];
        float4 dv = ((const float4*)adv)[d];
        __half2 e01 = __floats2half2_rn(__expf(lrelu(av.x + dv.x)),
                                        __expf(lrelu(av.y + dv.y)));
        __half2 e23 = __floats2half2_rn(__expf(lrelu(av.z + dv.z)),
                                        __expf(lrelu(av.w + dv.w)));
        uint2 u;
        u.x = *(unsigned int*)&e01;
        u.y = *(unsigned int*)&e23;
        lgu[pos] = u;
    }
    __syncthreads();

    {
        float4 bgv = make_float4(__ldg(bg + lane), __ldg(bg + 32 + lane),
                                 __ldg(bg + 64 + lane), __ldg(bg + 96 + lane));
        float btl = __ldg(bt + lane);
        float pwl = __ldg(pw + lane);
        float ssn = pwl * pwl;
        #pragma unroll
        for (int off = 16; off; off >>= 1) ssn += __shfl_xor_sync(0xffffffffu, ssn, off);
        float pwinv = rsqrtf(ssn);
        float* scr = scratch + warp * 128;
        float4* scr4 = (float4*)scr;
        for (int d = warp; d < KP1; d += 12) {
            int o0 = offs[d], dg = offs[d + 1] - o0;
            float slv = asv[d * 4 + (lane & 3)] + adv[d * 4 + (lane & 3)];
            float sev = __expf(lrelu(slv));
            float4 den;
            den.x = __shfl_sync(0xffffffffu, sev, 0);
            den.y = __shfl_sync(0xffffffffu, sev, 1);
            den.z = __shfl_sync(0xffffffffu, sev, 2);
            den.w = __shfl_sync(0xffffffffu, sev, 3);
            float4 xv = xp4[d * 32 + lane];
            float4 acc = {den.x * xv.x, den.y * xv.y, den.z * xv.z, den.w * xv.w};
            #pragma unroll 4
            for (int k = 0; k < dg; k++) {
                int s = srcl[o0 + k];
                uint2 lu = lgu[o0 + k];
                float2 f0 = __half22float2(*(__half2*)&lu.x);
                float2 f1 = __half22float2(*(__half2*)&lu.y);
                float4 xs = xp4[s * 32 + lane];
                acc.x += f0.x * xs.x; acc.y += f0.y * xs.y;
                acc.z += f1.x * xs.z; acc.w += f1.y * xs.w;
                den.x += f0.x; den.y += f0.y; den.z += f1.x; den.w += f1.y;
            }
            float4 r;
            r.x = fmaxf(__fdividef(acc.x, den.x) + bgv.x, 0.f);
            r.y = fmaxf(__fdividef(acc.y, den.y) + bgv.y, 0.f);
            r.z = fmaxf(__fdividef(acc.z, den.z) + bgv.z, 0.f);
            r.w = fmaxf(__fdividef(acc.w, den.w) + bgv.w, 0.f);
            scr[lane] = r.x; scr[32 + lane] = r.y;
            scr[64 + lane] = r.z; scr[96 + lane] = r.w;
            __syncwarp();
            float a = btl;
            #pragma unroll 8
            for (int c4 = 0; c4 < 32; c4++) {
                float4 rr = scr4[c4];
                float4 w = Wts4[c4 * 32 + lane];
                a += rr.x * w.x + rr.y * w.y + rr.z * w.z + rr.w * w.w;
            }
            g_hsh[(size_t)g * 4096 + d * 32 + lane] = a;
            float p = a * pwl;
            #pragma unroll
            for (int off = 16; off; off >>= 1) p += __shfl_xor_sync(0xffffffffu, p, off);
            if (lane == 0) score[d] = tanhf(p * pwinv);
            __syncwarp();
        }
    }
    __syncthreads();

    if (t < KP1) {
        float sc = score[t]; int r = 0;
        for (int m = 0; m < KP1; m++) {
            float v = score[m];
            r += (v > sc) || (v == sc && m < t);
        }
        nidx[t] = (r < KP2) ? 1 : 0;
    }
    __syncthreads();
    {
        int o = t & 31, grp = t >> 5;
        float m2 = -1e30f, su = 0.f;
        for (int n = grp; n < KP1; n += 12) {
            if (nidx[n]) {
                float v = g_hsh[(size_t)g * 4096 + n * 32 + o] * score[n];
                m2 = fmaxf(m2, v); su += v;
            }
        }
        red[grp * 32 + o] = m2; red2[grp * 32 + o] = su;
    }
    __syncthreads();
    if (t < 32) {
        float m2 = -1e30f, su = 0.f;
        #pragma unroll
        for (int k = 0; k < 12; k++) {
            m2 = fmaxf(m2, red[k * 32 + t]); su += red2[k * 32 + t];
        }
        g_gf[g * 64 + t]      = g_g1[g * 64 + t]      + m2;
        g_gf[g * 64 + 32 + t] = g_g1[g * 64 + 32 + t] + su / (float)KP2;
    }
}

// ============================================================================
// Stage 3: MLP 64 -> 256 -> 1024 -> 1. 128 blocks x 4 graphs.
// ============================================================================
__global__ __launch_bounds__(256, 1)
void mlp_kernel(const float* __restrict__ Wl1, const float* __restrict__ bl1,
                const float* __restrict__ Wl2, const float* __restrict__ bl2,
                const float* __restrict__ Wl3, const float* __restrict__ bl3,
                float* __restrict__ out)
{
    __shared__ float gsh[4][64];
    __shared__ __align__(16) float t1[4][256];
    __shared__ __align__(16) float wl3s[1024];
    __shared__ float redw[4][8];
    const int rb = blockIdx.x * 4;
    const int t = threadIdx.x, lane = t & 31, warp = t >> 5;

    for (int i = t; i < 1024; i += 256) wl3s[i] = Wl3[i];
    if (t < 256) ((float*)gsh)[t] = g_gf[rb * 64 + t];
    __syncthreads();
    for (int i = t; i < 1024; i += 256) {
        int r = i >> 8, j = i & 255;
        float a = bl1[j];
        #pragma unroll 8
        for (int k = 0; k < 64; k++) a += gsh[r][k] * Wl1[k * 256 + j];
        t1[r][j] = fmaxf(a, 0.f);
    }
    __syncthreads();
    const int jg = t;
    float4 acc[4];
    {
        float4 b2 = ((const float4*)bl2)[jg];
        #pragma unroll
        for (int r = 0; r < 4; r++) acc[r] = b2;
    }
    const float4* W2 = (const float4*)Wl2;
    for (int k4 = 0; k4 < 64; k4++) {
        float4 w0 = W2[(k4 * 4 + 0) * 256 + jg];
        float4 w1 = W2[(k4 * 4 + 1) * 256 + jg];
        float4 w2 = W2[(k4 * 4 + 2) * 256 + jg];
        float4 w3 = W2[(k4 * 4 + 3) * 256 + jg];
        #pragma unroll
        for (int r = 0; r < 4; r++) {
            float4 tv = ((const float4*)t1[r])[k4];
            acc[r].x += tv.x * w0.x + tv.y * w1.x + tv.z * w2.x + tv.w * w3.x;
            acc[r].y += tv.x * w0.y + tv.y * w1.y + tv.z * w2.y + tv.w * w3.y;
            acc[r].z += tv.x * w0.z + tv.y * w1.z + tv.z * w2.z + tv.w * w3.z;
            acc[r].w += tv.x * w0.w + tv.y * w1.w + tv.z * w2.w + tv.w * w3.w;
        }
    }
    float4 w3v = ((const float4*)wl3s)[jg];
    #pragma unroll
    for (int r = 0; r < 4; r++) {
        float p = fmaxf(acc[r].x, 0.f) * w3v.x + fmaxf(acc[r].y, 0.f) * w3v.y +
                  fmaxf(acc[r].z, 0.f) * w3v.z + fmaxf(acc[r].w, 0.f) * w3v.w;
        #pragma unroll
        for (int m = 16; m; m >>= 1) p += __shfl_xor_sync(0xffffffffu, p, m);
        if (lane == 0) redw[r][warp] = p;
    }
    __syncthreads();
    if (t < 4) {
        float s = bl3[0];
        #pragma unroll
        for (int w2 = 0; w2 < 8; w2++) s += redw[t][w2];
        out[rb + t] = s;
    }
}

// ============================================================================
extern "C" void kernel_launch(void* const* d_in, const int* in_sizes, int n_in,
                              void* d_out, int out_size)
{
    const float* x   = (const float*)d_in[0];
    const int*   ei  = (const int*)d_in[1];
    const float* Wg1 = (const float*)d_in[4];
    const float* as1 = (const float*)d_in[5];
    const float* ad1 = (const float*)d_in[6];
    const float* bg1 = (const float*)d_in[7];
    const float* Wt1 = (const float*)d_in[8];
    const float* bt1 = (const float*)d_in[9];
    const float* pw1 = (const float*)d_in[10];
    const float* Wg2 = (const float*)d_in[11];
    const float* as2 = (const float*)d_in[12];
    const float* ad2 = (const float*)d_in[13];
    const float* bg2 = (const float*)d_in[14];
    const float* Wt2 = (const float*)d_in[15];
    const float* bt2 = (const float*)d_in[16];
    const float* pw2 = (const float*)d_in[17];
    const float* Wl1 = (const float*)d_in[18];
    const float* bl1 = (const float*)d_in[19];
    const float* Wl2 = (const float*)d_in[20];
    const float* bl2 = (const float*)d_in[21];
    const float* Wl3 = (const float*)d_in[22];
    const float* bl3 = (const float*)d_in[23];
    float* out = (float*)d_out;

    const int SM1B = 112640;
    const int SM2B = 98304;
    cudaFuncSetAttribute(stage1_kernel, cudaFuncAttributeMaxDynamicSharedMemorySize, SM1B);
    cudaFuncSetAttribute(stage2_kernel, cudaFuncAttributeMaxDynamicSharedMemorySize, SM2B);

    stage1_kernel<<<NB, 384, SM1B>>>(x, ei, Wg1, as1, ad1, bg1, Wt1, bt1, pw1);
    stage2_kernel<<<NB, 384, SM2B>>>(Wg2, as2, ad2, bg2, Wt2, bt2, pw2);
    mlp_kernel<<<NB / 4, 256>>>(Wl1, bl1, Wl2, bl2, Wl3, bl3, out);
}